// round 1
// baseline (speedup 1.0000x reference)
#include <cuda_runtime.h>
#include <cuda_bf16.h>
#include <math_constants.h>

#define EPS 1e-8f
#define NTHREADS 1024
#define C_DIM 32000

// Row cached in dynamic shared memory (32000 floats = 128000 bytes).
// Phase 1: load + max. Phase 2: exp in place + sum. Phase 3: write output.
__global__ __launch_bounds__(NTHREADS, 1)
void smsoftmax_kernel(const float* __restrict__ logits,
                      const float* __restrict__ dist,
                      float* __restrict__ out) {
    extern __shared__ float4 row[];          // C_DIM/4 float4
    __shared__ float red[32];
    __shared__ float bcast[2];

    const int n4 = C_DIM / 4;
    const size_t row_off = (size_t)blockIdx.x * C_DIM;
    const float4* __restrict__ in4 = (const float4*)(logits + row_off);
    float4* __restrict__ out4 = (float4*)(out + row_off);

    const int tid  = threadIdx.x;
    const int lane = tid & 31;
    const int wid  = tid >> 5;

    // ---- Phase 1: load row into smem, thread-local max ----
    float m = -CUDART_INF_F;
    for (int i = tid; i < n4; i += NTHREADS) {
        float4 v = in4[i];
        row[i] = v;
        m = fmaxf(m, fmaxf(fmaxf(v.x, v.y), fmaxf(v.z, v.w)));
    }
    // block reduce max
    #pragma unroll
    for (int o = 16; o > 0; o >>= 1)
        m = fmaxf(m, __shfl_xor_sync(0xffffffffu, m, o));
    if (lane == 0) red[wid] = m;
    __syncthreads();
    if (wid == 0) {
        float t = red[lane];
        #pragma unroll
        for (int o = 16; o > 0; o >>= 1)
            t = fmaxf(t, __shfl_xor_sync(0xffffffffu, t, o));
        if (lane == 0) bcast[0] = t;
    }
    __syncthreads();
    m = bcast[0];

    // ---- Phase 2: e = exp(x - m + EPS) in place, thread-local sum ----
    float s = 0.0f;
    for (int i = tid; i < n4; i += NTHREADS) {
        float4 v = row[i];
        v.x = __expf(v.x - m + EPS);
        v.y = __expf(v.y - m + EPS);
        v.z = __expf(v.z - m + EPS);
        v.w = __expf(v.w - m + EPS);
        row[i] = v;
        s += (v.x + v.y) + (v.z + v.w);
    }
    // block reduce sum
    #pragma unroll
    for (int o = 16; o > 0; o >>= 1)
        s += __shfl_xor_sync(0xffffffffu, s, o);
    __syncthreads();          // protect red[] reuse
    if (lane == 0) red[wid] = s;
    __syncthreads();
    if (wid == 0) {
        float t = red[lane];
        #pragma unroll
        for (int o = 16; o > 0; o >>= 1)
            t += __shfl_xor_sync(0xffffffffu, t, o);
        if (lane == 0) bcast[1] = t;
    }
    __syncthreads();
    s = bcast[1];

    // ---- Phase 3: out_i = c*e_i / (c*e_i + s - e_i + EPS), c = exp(-dist) ----
    const float c = __expf(-__ldg(dist));
    for (int i = tid; i < n4; i += NTHREADS) {
        float4 v = row[i];
        float4 o;
        float ed;
        ed = v.x * c; o.x = ed / (ed + (s - v.x) + EPS);
        ed = v.y * c; o.y = ed / (ed + (s - v.y) + EPS);
        ed = v.z * c; o.z = ed / (ed + (s - v.z) + EPS);
        ed = v.w * c; o.w = ed / (ed + (s - v.w) + EPS);
        out4[i] = o;
    }
}

extern "C" void kernel_launch(void* const* d_in, const int* in_sizes, int n_in,
                              void* d_out, int out_size) {
    const float* logits = (const float*)d_in[0];
    const float* dist   = (const float*)d_in[1];
    float* out = (float*)d_out;

    const int B = in_sizes[0] / C_DIM;   // 4096 rows
    const size_t smem = (size_t)C_DIM * sizeof(float);   // 128000 B

    cudaFuncSetAttribute(smsoftmax_kernel,
                         cudaFuncAttributeMaxDynamicSharedMemorySize, (int)smem);
    smsoftmax_kernel<<<B, NTHREADS, smem>>>(logits, dist, out);
}

// round 3
// speedup vs baseline: 1.5666x; 1.5666x over previous
#include <cuda_runtime.h>
#include <cuda_bf16.h>
#include <math_constants.h>
#include <cstdint>

#define EPS      1e-8f
#define NT       1024
#define C_DIM    32000
#define N4       (C_DIM / 4)          // 8000 float4 per row
#define NITER    8                    // ceil(8000 / 1024)
#define ROW_BYTES (C_DIM * 4)         // 128000 bytes
#define GRID     152                  // GB300 SM count

__device__ __forceinline__ unsigned int smem_u32(const void* p) {
    return (unsigned int)__cvta_generic_to_shared(p);
}

__device__ __forceinline__ void mbar_wait(unsigned int mb, unsigned int parity) {
    asm volatile(
        "{\n\t"
        ".reg .pred P;\n\t"
        "WAIT_%=:\n\t"
        "mbarrier.try_wait.parity.acquire.cta.shared::cta.b64 P, [%0], %1, 0x989680;\n\t"
        "@P bra DONE_%=;\n\t"
        "bra WAIT_%=;\n\t"
        "DONE_%=:\n\t"
        "}"
        :: "r"(mb), "r"(parity) : "memory");
}

__global__ __launch_bounds__(NT, 1)
void smsoftmax_kernel(const float* __restrict__ logits,
                      const float* __restrict__ dist,
                      float* __restrict__ out, int B) {
    extern __shared__ float4 buf[];            // N4 float4 = 128000 B
    __shared__ __align__(8) unsigned long long mbar;
    __shared__ float red[32];
    __shared__ float bcast;

    const int tid  = threadIdx.x;
    const int lane = tid & 31;
    const int wid  = tid >> 5;
    const unsigned int mb  = smem_u32(&mbar);
    const unsigned int dst = smem_u32(buf);

    if (tid == 0) {
        asm volatile("mbarrier.init.shared.b64 [%0], 1;" :: "r"(mb) : "memory");
    }
    __syncthreads();

    // Kick off TMA for this CTA's first row.
    int row0 = blockIdx.x;
    if (tid == 0 && row0 < B) {
        const float* src = logits + (size_t)row0 * C_DIM;
        asm volatile("mbarrier.arrive.expect_tx.shared.b64 _, [%0], %1;"
                     :: "r"(mb), "r"((unsigned int)ROW_BYTES) : "memory");
        asm volatile("cp.async.bulk.shared::cluster.global.mbarrier::complete_tx::bytes "
                     "[%0], [%1], %2, [%3];"
                     :: "r"(dst), "l"(src), "r"((unsigned int)ROW_BYTES), "r"(mb) : "memory");
    }

    const float c = __expf(-__ldg(dist));
    unsigned int phase = 0;

    for (int row = blockIdx.x; row < B; row += GRID) {
        // ---- wait for TMA data ----
        mbar_wait(mb, phase);
        phase ^= 1u;

        // ---- drain smem -> registers, thread-local max ----
        float4 v[NITER];
        float m = -CUDART_INF_F;
        #pragma unroll
        for (int i = 0; i < NITER; i++) {
            int idx = i * NT + tid;
            if (idx < N4) {
                float4 t = buf[idx];
                v[i] = t;
                m = fmaxf(m, fmaxf(fmaxf(t.x, t.y), fmaxf(t.z, t.w)));
            }
        }
        __syncthreads();   // all threads done reading buf

        // ---- immediately prefetch next row into the same buffer ----
        int nrow = row + GRID;
        if (tid == 0 && nrow < B) {
            const float* src = logits + (size_t)nrow * C_DIM;
            asm volatile("mbarrier.arrive.expect_tx.shared.b64 _, [%0], %1;"
                         :: "r"(mb), "r"((unsigned int)ROW_BYTES) : "memory");
            asm volatile("cp.async.bulk.shared::cluster.global.mbarrier::complete_tx::bytes "
                         "[%0], [%1], %2, [%3];"
                         :: "r"(dst), "l"(src), "r"((unsigned int)ROW_BYTES), "r"(mb) : "memory");
        }

        // ---- block-reduce max ----
        #pragma unroll
        for (int o = 16; o > 0; o >>= 1)
            m = fmaxf(m, __shfl_xor_sync(0xffffffffu, m, o));
        if (lane == 0) red[wid] = m;
        __syncthreads();
        if (wid == 0) {
            float t = red[lane];
            #pragma unroll
            for (int o = 16; o > 0; o >>= 1)
                t = fmaxf(t, __shfl_xor_sync(0xffffffffu, t, o));
            if (lane == 0) bcast = t;
        }
        __syncthreads();
        m = bcast;

        // ---- exp in registers, thread-local sum ----
        float s = 0.0f;
        #pragma unroll
        for (int i = 0; i < NITER; i++) {
            int idx = i * NT + tid;
            if (idx < N4) {
                v[i].x = __expf(v[i].x - m + EPS);
                v[i].y = __expf(v[i].y - m + EPS);
                v[i].z = __expf(v[i].z - m + EPS);
                v[i].w = __expf(v[i].w - m + EPS);
                s += (v[i].x + v[i].y) + (v[i].z + v[i].w);
            }
        }

        // ---- block-reduce sum ----
        #pragma unroll
        for (int o = 16; o > 0; o >>= 1)
            s += __shfl_xor_sync(0xffffffffu, s, o);
        __syncthreads();   // bcast(max) reads done before overwrite
        if (lane == 0) red[wid] = s;
        __syncthreads();
        if (wid == 0) {
            float t = red[lane];
            #pragma unroll
            for (int o = 16; o > 0; o >>= 1)
                t += __shfl_xor_sync(0xffffffffu, t, o);
            if (lane == 0) bcast = t;
        }
        __syncthreads();
        s = bcast;

        // ---- out_i = c*e_i / (c*e_i + s - e_i + EPS), store (overlaps next TMA) ----
        float4* __restrict__ out4 = (float4*)(out + (size_t)row * C_DIM);
        #pragma unroll
        for (int i = 0; i < NITER; i++) {
            int idx = i * NT + tid;
            if (idx < N4) {
                float4 e = v[i];
                float4 o;
                float ed;
                ed = e.x * c; o.x = __fdividef(ed, ed + (s - e.x) + EPS);
                ed = e.y * c; o.y = __fdividef(ed, ed + (s - e.y) + EPS);
                ed = e.z * c; o.z = __fdividef(ed, ed + (s - e.z) + EPS);
                ed = e.w * c; o.w = __fdividef(ed, ed + (s - e.w) + EPS);
                out4[idx] = o;
            }
        }
        // next iteration's mbar_wait + post-LDS __syncthreads order red/bcast reuse
    }
}

extern "C" void kernel_launch(void* const* d_in, const int* in_sizes, int n_in,
                              void* d_out, int out_size) {
    const float* logits = (const float*)d_in[0];
    const float* dist   = (const float*)d_in[1];
    float* out = (float*)d_out;

    const int B = in_sizes[0] / C_DIM;                 // 4096 rows
    const size_t smem = (size_t)ROW_BYTES;             // 128000 B

    cudaFuncSetAttribute(smsoftmax_kernel,
                         cudaFuncAttributeMaxDynamicSharedMemorySize, (int)smem);
    smsoftmax_kernel<<<GRID, NT, smem>>>(logits, dist, out, B);
}

// round 4
// speedup vs baseline: 1.6557x; 1.0569x over previous
#include <cuda_runtime.h>
#include <cuda_bf16.h>
#include <cstdint>

#define EPS        1e-8f
#define NT         1024
#define C_DIM      32000
#define HALF_F     16000            // floats per half-row
#define HALF_F4    4000             // float4 per half-row
#define HALF_BYTES 64000
#define GRID       152              // GB300 SM count
#define LOG2E      1.4426950408889634f

__device__ __forceinline__ unsigned int smem_u32(const void* p) {
    return (unsigned int)__cvta_generic_to_shared(p);
}

__device__ __forceinline__ void mbar_wait(unsigned int mb, unsigned int parity) {
    asm volatile(
        "{\n\t"
        ".reg .pred P;\n\t"
        "WAIT_%=:\n\t"
        "mbarrier.try_wait.parity.acquire.cta.shared::cta.b64 P, [%0], %1, 0x989680;\n\t"
        "@P bra DONE_%=;\n\t"
        "bra WAIT_%=;\n\t"
        "DONE_%=:\n\t"
        "}"
        :: "r"(mb), "r"(parity) : "memory");
}

__device__ __forceinline__ void tma_issue(unsigned int mb, unsigned int dst,
                                          const float* src) {
    asm volatile("mbarrier.arrive.expect_tx.shared.b64 _, [%0], %1;"
                 :: "r"(mb), "r"((unsigned int)HALF_BYTES) : "memory");
    asm volatile("cp.async.bulk.shared::cluster.global.mbarrier::complete_tx::bytes "
                 "[%0], [%1], %2, [%3];"
                 :: "r"(dst), "l"(src), "r"((unsigned int)HALF_BYTES), "r"(mb)
                 : "memory");
}

// e = exp(x + EPS) via one FFMA + EX2
__device__ __forceinline__ float expe(float x) {
    return exp2f(fmaf(x, LOG2E, EPS * LOG2E));
}

__global__ __launch_bounds__(NT, 1)
void smsoftmax_kernel(const float* __restrict__ logits,
                      const float* __restrict__ dist,
                      float* __restrict__ out, int B) {
    extern __shared__ float4 buf[];               // 2 x HALF_F4 float4 = 128000 B
    __shared__ __align__(8) unsigned long long mbar0, mbar1;
    __shared__ float red[32];
    __shared__ float bcast;

    const int tid  = threadIdx.x;
    const int lane = tid & 31;
    const int wid  = tid >> 5;
    const unsigned int mb0  = smem_u32(&mbar0);
    const unsigned int mb1  = smem_u32(&mbar1);
    const unsigned int dst0 = smem_u32(buf);
    const unsigned int dst1 = dst0 + HALF_BYTES;

    if (tid == 0) {
        asm volatile("mbarrier.init.shared.b64 [%0], 1;" :: "r"(mb0) : "memory");
        asm volatile("mbarrier.init.shared.b64 [%0], 1;" :: "r"(mb1) : "memory");
    }
    __syncthreads();

    // Prologue: issue both halves of this CTA's first row.
    if (tid == 0 && blockIdx.x < B) {
        const float* base = logits + (size_t)blockIdx.x * C_DIM;
        tma_issue(mb0, dst0, base);
        tma_issue(mb1, dst1, base + HALF_F);
    }

    const float c   = __expf(-__ldg(dist));
    const float cm1 = c - 1.0f;
    unsigned int p0 = 0, p1 = 0;

    for (int row = blockIdx.x; row < B; row += GRID) {
        float4 v[8];
        float s = 0.0f;
        const int nrow = row + GRID;

        // ---- half 0: wait, fused drain + exp + partial sum ----
        mbar_wait(mb0, p0); p0 ^= 1u;
        #pragma unroll
        for (int j = 0; j < 4; j++) {
            int idx = j * NT + tid;
            if (idx < HALF_F4) {
                float4 t = buf[idx];
                t.x = expe(t.x); t.y = expe(t.y);
                t.z = expe(t.z); t.w = expe(t.w);
                s += (t.x + t.y) + (t.z + t.w);
                v[j] = t;
            }
        }
        __syncthreads();                       // all reads of buf0 done
        if (tid == 0 && nrow < B)
            tma_issue(mb0, dst0, logits + (size_t)nrow * C_DIM);

        // ---- half 1 ----
        mbar_wait(mb1, p1); p1 ^= 1u;
        #pragma unroll
        for (int j = 0; j < 4; j++) {
            int idx = j * NT + tid;
            if (idx < HALF_F4) {
                float4 t = buf[HALF_F4 + idx];
                t.x = expe(t.x); t.y = expe(t.y);
                t.z = expe(t.z); t.w = expe(t.w);
                s += (t.x + t.y) + (t.z + t.w);
                v[4 + j] = t;
            }
        }
        __syncthreads();                       // all reads of buf1 done
        if (tid == 0 && nrow < B)
            tma_issue(mb1, dst1, logits + (size_t)nrow * C_DIM + HALF_F);

        // ---- block-reduce sum ----
        #pragma unroll
        for (int o = 16; o > 0; o >>= 1)
            s += __shfl_xor_sync(0xffffffffu, s, o);
        if (lane == 0) red[wid] = s;
        __syncthreads();
        if (wid == 0) {
            float t = red[lane];
            #pragma unroll
            for (int o = 16; o > 0; o >>= 1)
                t += __shfl_xor_sync(0xffffffffu, t, o);
            if (lane == 0) bcast = t;
        }
        __syncthreads();
        const float t_s = bcast + EPS;         // s + EPS

        // ---- epilogue: out = c*e / ((c-1)*e + s + EPS) ----
        float4* __restrict__ out4 = (float4*)(out + (size_t)row * C_DIM);
        #pragma unroll
        for (int h = 0; h < 2; h++) {
            #pragma unroll
            for (int j = 0; j < 4; j++) {
                int idx = j * NT + tid;
                if (idx < HALF_F4) {
                    float4 e = v[h * 4 + j];
                    float4 o;
                    o.x = __fdividef(c * e.x, fmaf(cm1, e.x, t_s));
                    o.y = __fdividef(c * e.y, fmaf(cm1, e.y, t_s));
                    o.z = __fdividef(c * e.z, fmaf(cm1, e.z, t_s));
                    o.w = __fdividef(c * e.w, fmaf(cm1, e.w, t_s));
                    out4[h * HALF_F4 + idx] = o;
                }
            }
        }
    }
}

extern "C" void kernel_launch(void* const* d_in, const int* in_sizes, int n_in,
                              void* d_out, int out_size) {
    const float* logits = (const float*)d_in[0];
    const float* dist   = (const float*)d_in[1];
    float* out = (float*)d_out;

    const int B = in_sizes[0] / C_DIM;                 // 4096 rows
    const size_t smem = 2 * (size_t)HALF_BYTES;        // 128000 B

    cudaFuncSetAttribute(smsoftmax_kernel,
                         cudaFuncAttributeMaxDynamicSharedMemorySize, (int)smem);
    smsoftmax_kernel<<<GRID, NT, smem>>>(logits, dist, out, B);
}